// round 13
// baseline (speedup 1.0000x reference)
#include <cuda_runtime.h>

// ---------------------------------------------------------------------------
// MambaSSM: B=2, L=384, d_inner=384, d_state=384, dt_rank=384, d_conv=4
//
//   GEMM1 (fused): dt = softplus(x @ dt_w^T + dt_b)   -> g_DT   [768x384]
//                  x_dbl = x @ B_w^T                  -> g_XDBL [768x384]
//   GEMM2 (fused): Bm = x_dbl @ B_w^T -> g_BM ; Cm = x_dbl @ C_w^T -> g_CM
//        + conv row (blockIdx.y==12): u = silu(conv(x)+cb),
//          g_SC[b][d][l] = (dt, dt*u, u*D[d], 0)   (reads g_DT from GEMM1)
//   SCAN v5 (proven, byte-identical to the 108us kernel).
// ---------------------------------------------------------------------------

#define LOG2E 1.4426950408889634f

__device__ float  g_DT  [768 * 384];
__device__ float  g_XDBL[768 * 384];
__device__ float  g_BM  [768 * 384];
__device__ float  g_CM  [768 * 384];
__device__ float4 g_SC  [768 * 384];   // [b][d][l] : (dt, dt*u, u*D, 0)

__device__ __forceinline__ float ex2f(float x) {
    float y;
    asm("ex2.approx.ftz.f32 %0, %1;" : "=f"(y) : "f"(x));
    return y;
}

// ---------------------------------------------------------------------------
// Dual-output tiled SGEMM (v5, proven): 64x64 tiles.
// phase 0: grid (12,12): A=x, Wa=dt_w (softplus -> g_DT), Wb=B_w (-> g_XDBL)
// phase 1: grid (12,13): A=g_XDBL, Wa=B_w (-> g_BM), Wb=C_w (-> g_CM);
//          blockIdx.y==12 row runs the fused conv/silu/pack instead.
// ---------------------------------------------------------------------------
__global__ __launch_bounds__(256) void gemm_dual(
    const float* __restrict__ A_ext,
    const float* __restrict__ Wa,
    const float* __restrict__ Wb,
    const float* __restrict__ bias,
    const float* __restrict__ x,
    const float* __restrict__ convw,
    const float* __restrict__ convb,
    const float* __restrict__ Dvec,
    int phase)
{
    // ---- fused conv/silu/pack row (phase 1 only; grid.y == 13) ----
    if (blockIdx.y == 12) {
        const int tid = threadIdx.x;
        const int chg = blockIdx.x * 64 + (tid & 63);   // 0..767
        const int seg = tid >> 6;                        // 0..3
        const int b   = chg / 384;
        const int d   = chg - b * 384;
        const int l0  = seg * 96;

        const float c0 = convw[d * 4 + 0];
        const float c1 = convw[d * 4 + 1];
        const float c2 = convw[d * 4 + 2];
        const float c3 = convw[d * 4 + 3];
        const float cb = convb[d];
        const float Dd = Dvec[d];

        const float* xb  = x    + b * 147456 + d;
        const float* dtp = g_DT + b * 147456 + d;
        float4* scp = g_SC + (b * 384 + d) * 384;

        float w0 = (l0 >= 3) ? xb[(l0 - 3) * 384] : 0.f;
        float w1 = (l0 >= 2) ? xb[(l0 - 2) * 384] : 0.f;
        float w2 = (l0 >= 1) ? xb[(l0 - 1) * 384] : 0.f;

        for (int i = 0; i < 96; ++i) {
            const int l = l0 + i;
            const float w3 = xb[l * 384];
            float v = fmaf(w0, c0, fmaf(w1, c1, fmaf(w2, c2, fmaf(w3, c3, cb))));
            const float u  = v / (1.f + expf(-v));     // silu
            const float dt = dtp[l * 384];
            scp[l] = make_float4(dt, dt * u, u * Dd, 0.f);
            w0 = w1; w1 = w2; w2 = w3;
        }
        return;
    }

    __shared__ float As[16][64];
    __shared__ float Bs[16][64];

    const float* A  = (phase == 0) ? A_ext : g_XDBL;
    float*       Ca = (phase == 0) ? g_DT  : g_BM;
    float*       Cb = (phase == 0) ? g_XDBL: g_CM;

    const int tid = threadIdx.x;
    const int m0  = blockIdx.x * 64;
    const int bn  = blockIdx.y;            // 0..11
    const bool second = (bn >= 6);
    const float* W  = second ? Wb : Wa;
    float*       Cc = second ? Cb : Ca;
    const bool doAct = (phase == 0) && !second;
    const int n0 = (second ? bn - 6 : bn) * 64;

    const int loadRow = tid >> 2;          // 0..63
    const int loadCol = (tid & 3) << 2;    // 0,4,8,12
    const float* Ap = A + (m0 + loadRow) * 384 + loadCol;
    const float* Wp = W + (n0 + loadRow) * 384 + loadCol;

    float4 aR = *(const float4*)Ap;
    float4 wR = *(const float4*)Wp;

    float acc[4][4];
#pragma unroll
    for (int i = 0; i < 4; i++)
#pragma unroll
        for (int j = 0; j < 4; j++) acc[i][j] = 0.f;

    const int tx = tid & 15;
    const int ty = tid >> 4;

    for (int kt = 0; kt < 24; ++kt) {
        As[loadCol + 0][loadRow] = aR.x;
        As[loadCol + 1][loadRow] = aR.y;
        As[loadCol + 2][loadRow] = aR.z;
        As[loadCol + 3][loadRow] = aR.w;
        Bs[loadCol + 0][loadRow] = wR.x;
        Bs[loadCol + 1][loadRow] = wR.y;
        Bs[loadCol + 2][loadRow] = wR.z;
        Bs[loadCol + 3][loadRow] = wR.w;
        __syncthreads();

        if (kt < 23) {
            aR = *(const float4*)(Ap + (kt + 1) * 16);
            wR = *(const float4*)(Wp + (kt + 1) * 16);
        }

#pragma unroll
        for (int k = 0; k < 16; ++k) {
            float4 av = *(const float4*)&As[k][ty << 2];
            float4 bv = *(const float4*)&Bs[k][tx << 2];
            float a[4] = {av.x, av.y, av.z, av.w};
            float b[4] = {bv.x, bv.y, bv.z, bv.w};
#pragma unroll
            for (int i = 0; i < 4; i++)
#pragma unroll
                for (int j = 0; j < 4; j++)
                    acc[i][j] = fmaf(a[i], b[j], acc[i][j]);
        }
        __syncthreads();
    }

#pragma unroll
    for (int i = 0; i < 4; i++) {
        const int m = m0 + (ty << 2) + i;
#pragma unroll
        for (int j = 0; j < 4; j++) {
            const int n = n0 + (tx << 2) + j;
            float v = acc[i][j];
            if (doAct) {
                v += bias[n];
                v = fmaxf(v, 0.f) + log1pf(expf(-fabsf(v)));
            }
            Cc[m * 384 + n] = v;
        }
    }
}

// ---------------------------------------------------------------------------
// SCAN v5 (proven, unchanged): grid 384, block 384. CTA = 2 channels.
// tid 0..191 -> channel d0 (s2 = tid); tid 192..383 -> channel d0+1.
// ---------------------------------------------------------------------------
#define TL 48   // l-tile between smem reductions (384/48 = 8 tiles)

__global__ __launch_bounds__(384) void scan_kernel(
    const float* __restrict__ A_log,
    float* __restrict__ out)
{
    __shared__ float  part[2][TL][49];     // [ch][l_in_tile][48 partials + pad]
    __shared__ float4 scbuf[2][2][TL];     // [buf][ch][l_in_tile]

    const int tid  = threadIdx.x;
    const int lane = tid & 31;
    const int ch   = tid >= 192;
    const int s2   = tid - ch * 192;        // float2-state index 0..191
    const int wid6 = (tid >> 5) - ch * 6;   // warp index within channel 0..5

    const int pid   = blockIdx.x;           // 0..383
    const int b     = pid / 192;
    const int dbase = (pid - b * 192) * 2;
    const int d     = dbase + ch;

    // Per-thread invariants
    const float2 a = ((const float2*)(A_log + d * 384))[s2];
    const float A2x = -ex2f(a.x * LOG2E) * LOG2E;
    const float A2y = -ex2f(a.y * LOG2E) * LOG2E;
    const float2 bm = ((const float2*)(g_BM + (b * 384 + d) * 384))[s2];
    float hx = 0.f, hy = 0.f;

    const float4* scp0 = g_SC + (b * 384 + dbase) * 384;   // channel-0 stream
    const float2* Cb2  = (const float2*)(g_CM + b * 147456) + s2;

    // Preload tile 0 sc (threads 0..95: c = tid/48, li = tid%48)
    if (tid < 96) {
        const int c = tid / TL, li = tid - c * TL;
        scbuf[0][c][li] = __ldg(scp0 + c * 384 + li);
    }
    // Prefetch C rows l=0,1
    float2 C0 = __ldg(Cb2);
    float2 C1 = __ldg(Cb2 + 192);
    __syncthreads();

    float accP = 0.f;

    for (int tile = 0; tile < 8; ++tile) {
        const int lbase = tile * TL;
        const int buf   = tile & 1;

#pragma unroll 6
        for (int i = 0; i < TL; ++i) {
            const int l = lbase + i;
            const float4 sc = scbuf[buf][ch][i];   // LDS broadcast
            const float2 Cv = C0;
            C0 = C1;
            const int lpf = (l + 2 < 384) ? (l + 2) : 383;
            C1 = __ldg(Cb2 + lpf * 192);

            const float e0 = ex2f(sc.x * A2x);
            hx = fmaf(e0, hx, sc.y * bm.x);
            const float e1 = ex2f(sc.x * A2y);
            hy = fmaf(e1, hy, sc.y * bm.y);
            const float acc = fmaf(hy, Cv.y, hx * Cv.x);

            if (i > 0) {   // deferred: reduce previous iteration's partial
                accP += __shfl_xor_sync(0xffffffffu, accP, 16);
                accP += __shfl_xor_sync(0xffffffffu, accP, 8);
                if (lane < 8) part[ch][i - 1][wid6 * 8 + lane] = accP;
            }
            accP = acc;
        }
        // flush last iteration of the tile
        accP += __shfl_xor_sync(0xffffffffu, accP, 16);
        accP += __shfl_xor_sync(0xffffffffu, accP, 8);
        if (lane < 8) part[ch][TL - 1][wid6 * 8 + lane] = accP;
        __syncthreads();

        // Reduce + write out (tid<96); load next tile's sc (tid 96..191)
        if (tid < 96) {
            const int c  = tid / TL;
            const int li = tid - c * TL;
            const float* p = part[c][li];
            float t0 = 0.f, t1 = 0.f, t2 = 0.f, t3 = 0.f;
#pragma unroll
            for (int j = 0; j < 48; j += 4) {
                t0 += p[j]; t1 += p[j + 1]; t2 += p[j + 2]; t3 += p[j + 3];
            }
            const int l = lbase + li;
            float y = (t0 + t1) + (t2 + t3);
            y += scbuf[buf][c][li].z;              // u*D term
            out[(size_t)b * 147456 + (size_t)l * 384 + dbase + c] = y;
        } else if (tid < 192 && tile < 7) {
            const int t2i = tid - 96;
            const int c = t2i / TL, li = t2i - c * TL;
            scbuf[buf ^ 1][c][li] = __ldg(scp0 + c * 384 + lbase + TL + li);
        }
        __syncthreads();
    }
}

// ---------------------------------------------------------------------------
extern "C" void kernel_launch(void* const* d_in, const int* in_sizes, int n_in,
                              void* d_out, int out_size)
{
    const float* x      = (const float*)d_in[0];
    const float* A_log  = (const float*)d_in[1];
    const float* Dvec   = (const float*)d_in[2];
    const float* dt_w   = (const float*)d_in[3];
    const float* dt_b   = (const float*)d_in[4];
    const float* B_w    = (const float*)d_in[5];
    const float* C_w    = (const float*)d_in[6];
    const float* conv_w = (const float*)d_in[7];
    const float* conv_b = (const float*)d_in[8];
    float* out = (float*)d_out;

    // GEMM1: dt (softplus) + x_dbl
    gemm_dual<<<dim3(12, 12), 256>>>(x, dt_w, B_w, dt_b,
                                     x, conv_w, conv_b, Dvec, 0);
    // GEMM2: Bm + Cm, with fused conv/silu/pack row (blockIdx.y == 12)
    gemm_dual<<<dim3(12, 13), 256>>>(x, B_w, C_w, nullptr,
                                     x, conv_w, conv_b, Dvec, 1);
    // Scan
    scan_kernel<<<384, 384>>>(A_log, out);
}

// round 14
// speedup vs baseline: 1.3147x; 1.3147x over previous
#include <cuda_runtime.h>

// ---------------------------------------------------------------------------
// MambaSSM: B=2, L=384, d_inner=384, d_state=384, dt_rank=384, d_conv=4
//
//   GEMM1 (fused): dt = softplus(x @ dt_w^T + dt_b)   -> g_DT   [768x384]
//                  x_dbl = x @ B_w^T                  -> g_XDBL [768x384]
//   GEMM2 (fused): Bm = x_dbl @ B_w^T -> g_BM ; Cm = x_dbl @ C_w^T -> g_CM
//   SCAN v14 = v5 + in-prologue conv/silu/pack (conv kernel + g_SC removed):
//     CTA = 2 channels x 192 float2-lanes = 384 threads, grid 384.
//     prologue: each thread computes sc=(dt, dt*u, u*D) for 2 l's -> smem scS.
//     loop: identical to v5 but sc read from scS (no double-buffer reload).
// ---------------------------------------------------------------------------

#define LOG2E 1.4426950408889634f

__device__ float g_DT  [768 * 384];
__device__ float g_XDBL[768 * 384];
__device__ float g_BM  [768 * 384];
__device__ float g_CM  [768 * 384];

__device__ __forceinline__ float ex2f(float x) {
    float y;
    asm("ex2.approx.ftz.f32 %0, %1;" : "=f"(y) : "f"(x));
    return y;
}

// ---------------------------------------------------------------------------
// Dual-output tiled SGEMM (v5, proven): 64x64 tiles, grid (12,12).
// phase 0: A=x,      Wa=dt_w (bias+softplus -> g_DT), Wb=B_w (-> g_XDBL)
// phase 1: A=g_XDBL, Wa=B_w  (-> g_BM),               Wb=C_w (-> g_CM)
// ---------------------------------------------------------------------------
__global__ __launch_bounds__(256) void gemm_dual(
    const float* __restrict__ A_ext,
    const float* __restrict__ Wa,
    const float* __restrict__ Wb,
    const float* __restrict__ bias,
    int phase)
{
    __shared__ float As[16][64];
    __shared__ float Bs[16][64];

    const float* A  = (phase == 0) ? A_ext : g_XDBL;
    float*       Ca = (phase == 0) ? g_DT  : g_BM;
    float*       Cb = (phase == 0) ? g_XDBL: g_CM;

    const int tid = threadIdx.x;
    const int m0  = blockIdx.x * 64;
    const int bn  = blockIdx.y;            // 0..11
    const bool second = (bn >= 6);
    const float* W  = second ? Wb : Wa;
    float*       Cc = second ? Cb : Ca;
    const bool doAct = (phase == 0) && !second;
    const int n0 = (second ? bn - 6 : bn) * 64;

    const int loadRow = tid >> 2;          // 0..63
    const int loadCol = (tid & 3) << 2;    // 0,4,8,12
    const float* Ap = A + (m0 + loadRow) * 384 + loadCol;
    const float* Wp = W + (n0 + loadRow) * 384 + loadCol;

    float4 aR = *(const float4*)Ap;
    float4 wR = *(const float4*)Wp;

    float acc[4][4];
#pragma unroll
    for (int i = 0; i < 4; i++)
#pragma unroll
        for (int j = 0; j < 4; j++) acc[i][j] = 0.f;

    const int tx = tid & 15;
    const int ty = tid >> 4;

    for (int kt = 0; kt < 24; ++kt) {
        As[loadCol + 0][loadRow] = aR.x;
        As[loadCol + 1][loadRow] = aR.y;
        As[loadCol + 2][loadRow] = aR.z;
        As[loadCol + 3][loadRow] = aR.w;
        Bs[loadCol + 0][loadRow] = wR.x;
        Bs[loadCol + 1][loadRow] = wR.y;
        Bs[loadCol + 2][loadRow] = wR.z;
        Bs[loadCol + 3][loadRow] = wR.w;
        __syncthreads();

        if (kt < 23) {
            aR = *(const float4*)(Ap + (kt + 1) * 16);
            wR = *(const float4*)(Wp + (kt + 1) * 16);
        }

#pragma unroll
        for (int k = 0; k < 16; ++k) {
            float4 av = *(const float4*)&As[k][ty << 2];
            float4 bv = *(const float4*)&Bs[k][tx << 2];
            float a[4] = {av.x, av.y, av.z, av.w};
            float b[4] = {bv.x, bv.y, bv.z, bv.w};
#pragma unroll
            for (int i = 0; i < 4; i++)
#pragma unroll
                for (int j = 0; j < 4; j++)
                    acc[i][j] = fmaf(a[i], b[j], acc[i][j]);
        }
        __syncthreads();
    }

#pragma unroll
    for (int i = 0; i < 4; i++) {
        const int m = m0 + (ty << 2) + i;
#pragma unroll
        for (int j = 0; j < 4; j++) {
            const int n = n0 + (tx << 2) + j;
            float v = acc[i][j];
            if (doAct) {
                v += bias[n];
                v = fmaxf(v, 0.f) + log1pf(expf(-fabsf(v)));
            }
            Cc[m * 384 + n] = v;
        }
    }
}

// ---------------------------------------------------------------------------
// SCAN v14: grid 384, block 384. CTA = 2 channels of one batch.
// Prologue computes conv+silu+pack into smem scS; loop identical to v5.
// ---------------------------------------------------------------------------
#define TL 48   // l-tile between smem reductions (384/48 = 8 tiles)

__global__ __launch_bounds__(384) void scan_kernel(
    const float* __restrict__ A_log,
    const float* __restrict__ x,
    const float* __restrict__ convw,
    const float* __restrict__ convb,
    const float* __restrict__ Dvec,
    float* __restrict__ out)
{
    __shared__ float  part[2][TL][49];   // [ch][l_in_tile][48 partials + pad]
    __shared__ float4 scS[2][384];       // [ch][l] : (dt, dt*u, u*D, 0)

    const int tid  = threadIdx.x;
    const int lane = tid & 31;
    const int ch   = tid >= 192;
    const int s2   = tid - ch * 192;        // float2-state index 0..191
    const int wid6 = (tid >> 5) - ch * 6;   // warp index within channel 0..5

    const int pid   = blockIdx.x;           // 0..383
    const int b     = pid / 192;
    const int dbase = (pid - b * 192) * 2;
    const int d     = dbase + ch;

    // ---- prologue: conv + silu + pack for this CTA's 2 channels ----
    {
        const float c0 = convw[d * 4 + 0];
        const float c1 = convw[d * 4 + 1];
        const float c2 = convw[d * 4 + 2];
        const float c3 = convw[d * 4 + 3];
        const float cb = convb[d];
        const float Dd = Dvec[d];
        const float* xb  = x    + b * 147456 + d;
        const float* dtp = g_DT + b * 147456 + d;
        const int l0 = s2 * 2;

        const float xm3 = (l0 >= 3) ? xb[(l0 - 3) * 384] : 0.f;
        const float xm2 = (l0 >= 2) ? xb[(l0 - 2) * 384] : 0.f;
        const float xm1 = (l0 >= 1) ? xb[(l0 - 1) * 384] : 0.f;
        const float x0  = xb[l0 * 384];
        const float x1  = xb[(l0 + 1) * 384];
        const float dt0 = dtp[l0 * 384];
        const float dt1 = dtp[(l0 + 1) * 384];

        const float v0 = fmaf(xm3, c0, fmaf(xm2, c1, fmaf(xm1, c2, fmaf(x0, c3, cb))));
        const float v1 = fmaf(xm2, c0, fmaf(xm1, c1, fmaf(x0,  c2, fmaf(x1, c3, cb))));
        const float u0 = v0 / (1.f + expf(-v0));   // silu
        const float u1 = v1 / (1.f + expf(-v1));

        scS[ch][l0]     = make_float4(dt0, dt0 * u0, u0 * Dd, 0.f);
        scS[ch][l0 + 1] = make_float4(dt1, dt1 * u1, u1 * Dd, 0.f);
    }

    // Per-thread invariants
    const float2 a = ((const float2*)(A_log + d * 384))[s2];
    const float A2x = -ex2f(a.x * LOG2E) * LOG2E;
    const float A2y = -ex2f(a.y * LOG2E) * LOG2E;
    const float2 bm = ((const float2*)(g_BM + (b * 384 + d) * 384))[s2];
    float hx = 0.f, hy = 0.f;

    const float2* Cb2 = (const float2*)(g_CM + b * 147456) + s2;

    // Prefetch C rows l=0,1
    float2 C0 = __ldg(Cb2);
    float2 C1 = __ldg(Cb2 + 192);
    __syncthreads();   // scS visible

    float accP = 0.f;

    for (int tile = 0; tile < 8; ++tile) {
        const int lbase = tile * TL;

#pragma unroll 6
        for (int i = 0; i < TL; ++i) {
            const int l = lbase + i;
            const float4 sc = scS[ch][l];          // LDS broadcast
            const float2 Cv = C0;
            C0 = C1;
            const int lpf = (l + 2 < 384) ? (l + 2) : 383;
            C1 = __ldg(Cb2 + lpf * 192);

            const float e0 = ex2f(sc.x * A2x);
            hx = fmaf(e0, hx, sc.y * bm.x);
            const float e1 = ex2f(sc.x * A2y);
            hy = fmaf(e1, hy, sc.y * bm.y);
            const float acc = fmaf(hy, Cv.y, hx * Cv.x);

            if (i > 0) {   // deferred: reduce previous iteration's partial
                accP += __shfl_xor_sync(0xffffffffu, accP, 16);
                accP += __shfl_xor_sync(0xffffffffu, accP, 8);
                if (lane < 8) part[ch][i - 1][wid6 * 8 + lane] = accP;
            }
            accP = acc;
        }
        // flush last iteration of the tile
        accP += __shfl_xor_sync(0xffffffffu, accP, 16);
        accP += __shfl_xor_sync(0xffffffffu, accP, 8);
        if (lane < 8) part[ch][TL - 1][wid6 * 8 + lane] = accP;
        __syncthreads();

        // Reduce + write out (tid < 96)
        if (tid < 96) {
            const int c  = tid / TL;
            const int li = tid - c * TL;
            const float* p = part[c][li];
            float t0 = 0.f, t1 = 0.f, t2 = 0.f, t3 = 0.f;
#pragma unroll
            for (int j = 0; j < 48; j += 4) {
                t0 += p[j]; t1 += p[j + 1]; t2 += p[j + 2]; t3 += p[j + 3];
            }
            const int l = lbase + li;
            float y = (t0 + t1) + (t2 + t3);
            y += scS[c][l].z;                      // u*D term
            out[(size_t)b * 147456 + (size_t)l * 384 + dbase + c] = y;
        }
        __syncthreads();
    }
}

// ---------------------------------------------------------------------------
extern "C" void kernel_launch(void* const* d_in, const int* in_sizes, int n_in,
                              void* d_out, int out_size)
{
    const float* x      = (const float*)d_in[0];
    const float* A_log  = (const float*)d_in[1];
    const float* Dvec   = (const float*)d_in[2];
    const float* dt_w   = (const float*)d_in[3];
    const float* dt_b   = (const float*)d_in[4];
    const float* B_w    = (const float*)d_in[5];
    const float* C_w    = (const float*)d_in[6];
    const float* conv_w = (const float*)d_in[7];
    const float* conv_b = (const float*)d_in[8];
    float* out = (float*)d_out;

    // GEMM1: dt (softplus) + x_dbl
    gemm_dual<<<dim3(12, 12), 256>>>(x, dt_w, B_w, dt_b, 0);
    // GEMM2: Bm + Cm
    gemm_dual<<<dim3(12, 12), 256>>>(x, B_w, C_w, nullptr, 1);
    // Scan (conv/silu/pack fused into prologue)
    scan_kernel<<<384, 384>>>(A_log, x, conv_w, conv_b, Dvec, out);
}